// round 17
// baseline (speedup 1.0000x reference)
#include <cuda_runtime.h>
#include <cuda_bf16.h>

#define TT     512
#define BN     8192
#define NTOT   (TT * BN)          // 4,194,304
#define BPB    32                 // batch elements per block
#define GRID   (BN / BPB)         // 256 blocks
#define BLK    256                // 32 batch x 8 sub-chunks
#define NSUB   8                  // sub-chunks per tile
#define TSUB   8                  // timesteps per sub-chunk
#define TILE_T (NSUB * TSUB)      // 64 timesteps per tile
#define NTILE  (TT / TILE_T)      // 8 tiles

#define GAMMA_F 0.99f

// Only cross-block state: per-block loss partials + epoch counter.
__device__ float g_part[2 * GRID];
__device__ unsigned int g_ctr;    // monotonic; epoch-based (no reset needed)

__device__ __forceinline__ float frcp(float x) {
    float r;
    asm("rcp.approx.f32 %0, %1;" : "=f"(r) : "f"(x));
    return r;
}

// ---------------------------------------------------------------------------
// Single fused kernel. Block owns batch column [32) x all time, walked in
// 8 DESCENDING 64-step tiles, so the V-trace carry flows tile-to-tile
// inside the block (smem). Zero scratch traffic to DRAM.
//   Phase A (per tile): stream inputs once -> smem payload + sub-chunk (A,B)
//   Phase B: per-thread entry carry = right-fold of later sub-chunk maps
//   Phase C: replay 8 steps from smem; accumulate actor/critic
// ---------------------------------------------------------------------------
__global__ void __launch_bounds__(BLK)
fused(const float2* __restrict__ prob,
      const float2* __restrict__ aprob,
      const float*  __restrict__ v,
      const float*  __restrict__ rew,
      const int*    __restrict__ act,
      const int*    __restrict__ dn,
      const float*  __restrict__ nv,
      float*        __restrict__ out)
{
    __shared__ float s_rat[TILE_T][BPB];   // ratio, done bit in sign (8 KB)
    __shared__ float s_v  [TILE_T][BPB];   // 8 KB
    __shared__ float s_r  [TILE_T][BPB];   // 8 KB
    __shared__ float s_A[NSUB][BPB];       // 1 KB
    __shared__ float s_B[NSUB][BPB];       // 1 KB
    __shared__ float s_carry[BPB];

    const int bl  = threadIdx.x & 31;      // batch element within block
    const int sub = threadIdx.x >> 5;      // sub-chunk (== warp id)
    const int bg  = blockIdx.x * BPB + bl; // global batch element

    // initial carry: next_v at the last timestep
    if (sub == 0)
        s_carry[bl] = __ldg(&nv[(TT - 1) * BN + bg]);

    float actor = 0.0f, critic = 0.0f;

    for (int tile = NTILE - 1; tile >= 0; tile--) {
        const int t0 = tile * TILE_T + sub * TSUB;

        // ---- Phase A: stream inputs; build payload + sub-chunk affine
        float A = 1.0f, B = 0.0f;
        #pragma unroll
        for (int i = 0; i < TSUB; i++) {
            const int idx = (t0 + i) * BN + bg;   // warp: 32 consecutive bg

            const float2 p  = __ldcs(&prob[idx]);
            const float2 ap = __ldcs(&aprob[idx]);
            const int    a  = __ldcs(&act[idx]);
            const int    d  = __ldcs(&dn[idx]);
            const float  vv = __ldcs(&v[idx]);
            const float  rr = __ldcs(&rew[idx]);

            const float pa   = a ? p.y  : p.x;
            const float apa  = a ? ap.y : ap.x;
            const float rat  = (pa * (ap.x + ap.y)) * frcp((p.x + p.y) * apa);
            const float g    = d ? 0.0f : GAMMA_F;
            const float rho  = fminf(rat, 1.0f);
            const float Bt   = fmaf(rho, rr - vv, vv);

            B = fmaf(A, Bt, B);                  // F <- F o f_t (ascending)
            A = A * (rho * g);

            const int tl = sub * TSUB + i;
            s_rat[tl][bl] =
                __uint_as_float(__float_as_uint(rat) | ((unsigned)d << 31));
            s_v[tl][bl] = vv;
            s_r[tl][bl] = rr;
        }
        s_A[sub][bl] = A;
        s_B[sub][bl] = B;
        __syncthreads();   // payload + (A,B) visible; carry stable to read

        // ---- Phase B: entry carry for this sub-chunk (fixed-order fold)
        float E = s_carry[bl];
        #pragma unroll
        for (int ss = NSUB - 1; ss > 0; ss--) {   // compile-time bound
            if (ss > sub)
                E = fmaf(s_A[ss][bl], E, s_B[ss][bl]);
        }
        __syncthreads();   // everyone has read s_carry; safe to overwrite

        // sub 0's exit == carry entering the next (earlier) tile
        if (sub == 0)
            s_carry[bl] = fmaf(A, E, B);

        // ---- Phase C: replay descending time from smem
        #pragma unroll
        for (int k = TSUB - 1; k >= 0; k--) {
            const int tl = sub * TSUB + k;
            const unsigned u = __float_as_uint(s_rat[tl][bl]);
            const float ratio = __uint_as_float(u & 0x7fffffffu);
            const float g    = (u >> 31) ? 0.0f : GAMMA_F;
            const float vv   = s_v[tl][bl];
            const float rr   = s_r[tl][bl];
            const float rho  = fminf(ratio, 1.0f);
            const float adv  = rho * (rr + g * E - vv);
            critic = fmaf(adv, adv, critic);
            const float cl = fminf(fmaxf(ratio, 0.8f), 1.2f);
            actor += fminf(ratio * adv, cl * adv);
            E = vv + adv;
        }
        __syncthreads();   // replay done before next tile overwrites payload
    }

    // ---- deterministic block reduction (8 warps)
    __shared__ float sa[8], sc[8];
    #pragma unroll
    for (int o = 16; o > 0; o >>= 1) {
        actor  += __shfl_down_sync(0xffffffffu, actor,  o);
        critic += __shfl_down_sync(0xffffffffu, critic, o);
    }
    if ((threadIdx.x & 31) == 0) { sa[sub] = actor; sc[sub] = critic; }
    __syncthreads();
    if (threadIdx.x == 0) {
        float Asum = 0.0f, Csum = 0.0f;
        #pragma unroll
        for (int k = 0; k < 8; k++) { Asum += sa[k]; Csum += sc[k]; }
        g_part[blockIdx.x]        = Asum;
        g_part[GRID + blockIdx.x] = Csum;
    }

    // ---- last block (epoch-based) does the final deterministic reduction
    __shared__ bool is_last;
    if (threadIdx.x == 0) {
        __threadfence();
        const unsigned n = atomicAdd(&g_ctr, 1u);
        is_last = ((n % GRID) == (unsigned)(GRID - 1));
    }
    __syncthreads();
    if (is_last) {
        const int t = threadIdx.x;
        __shared__ float ra[BLK], rc[BLK];
        ra[t] = g_part[t];          // GRID == BLK == 256
        rc[t] = g_part[GRID + t];
        __syncthreads();
        #pragma unroll
        for (int s = BLK / 2; s > 0; s >>= 1) {
            if (t < s) { ra[t] += ra[t + s]; rc[t] += rc[t + s]; }
            __syncthreads();
        }
        if (t == 0) {
            const float inv = 1.0f / (float)NTOT;
            out[0] = (-ra[0] + 0.5f * rc[0]) * inv;
        }
    }
}

extern "C" void kernel_launch(void* const* d_in, const int* in_sizes, int n_in,
                              void* d_out, int out_size)
{
    const float2* prob  = (const float2*)d_in[0];
    const float2* aprob = (const float2*)d_in[1];
    const float*  v     = (const float*)d_in[2];
    const float*  nv    = (const float*)d_in[3];
    const float*  rew   = (const float*)d_in[4];
    const int*    act   = (const int*)d_in[5];
    const int*    dn    = (const int*)d_in[6];
    float* out = (float*)d_out;

    fused<<<GRID, BLK>>>(prob, aprob, v, rew, act, dn, nv, out);
}